// round 1
// baseline (speedup 1.0000x reference)
#include <cuda_runtime.h>
#include <cstdint>

#define BN 8192
#define CN 8192
#define DK 256

typedef unsigned long long ull;

// ---------------- scratch (device globals: no allocation allowed) ----------
__device__ float g_sqx[BN];
__device__ float g_sqc[CN];
__device__ float g_colsum[CN];
__device__ unsigned g_rowmin_bits[BN];   // fp32 bits of min_{c != label} dist(x_i, c)
__device__ ull g_rowpack[CN];            // (fp32bits << 32) | argmin col (c != r)
__device__ float g_dpos[BN];
__device__ int g_lab32;                  // 1 if labels buffer is int32, 0 if int64

// ---------------- init ------------------------------------------------------
__global__ void init_kernel() {
    int i = blockIdx.x * blockDim.x + threadIdx.x;
    if (i < CN) {
        g_colsum[i] = 0.0f;
        g_rowmin_bits[i] = 0x7F7FFFFFu;            // FLT_MAX bits
        g_rowpack[i] = 0xFFFFFFFFFFFFFFFFull;
    }
    if (i == 0) g_lab32 = 0;
}

// Detect labels dtype: int64-LE => odd 32-bit words (high halves) are all zero.
__global__ void detect_kernel(const unsigned* __restrict__ lw) {
    int i = blockIdx.x * blockDim.x + threadIdx.x;   // 0 .. BN/2-1
    if (i < BN / 2) {
        if (lw[2 * i + 1] != 0u) g_lab32 = 1;        // benign race (same value)
    }
}

// ---------------- squared norms --------------------------------------------
__global__ void sqnorm_kernel(const float* __restrict__ X, int nrows, int which) {
    int warp = (blockIdx.x * blockDim.x + threadIdx.x) >> 5;
    int lane = threadIdx.x & 31;
    if (warp >= nrows) return;
    const float4* p = reinterpret_cast<const float4*>(X + (size_t)warp * DK);
    float s = 0.0f;
#pragma unroll
    for (int q = 0; q < 2; q++) {
        float4 v = p[lane * 2 + q];
        s += v.x * v.x + v.y * v.y + v.z * v.z + v.w * v.w;
    }
#pragma unroll
    for (int o = 16; o; o >>= 1) s += __shfl_xor_sync(0xffffffffu, s, o);
    if (lane == 0) {
        if (which == 0) g_sqx[warp] = s; else g_sqc[warp] = s;
    }
}

// ---------------- fused distance GEMM ---------------------------------------
// MODE 1: distmat(x, centers): per-row d_pos + min_{c != label}  (nothing stored)
// MODE 2: distmat(centers, centers): store tile to out3, per-row argmin (c != r),
//         column sums.
// Tile: 128 rows x 128 cols per chunk; each block owns 128 rows x 1024 cols
// (8 chunks). Grid (8 col-splits, 64 row-blocks) = 512 blocks.
template <int MODE>
__global__ void __launch_bounds__(256) distmat_kernel(
    const float* __restrict__ A, const float* __restrict__ Bm,
    const void* __restrict__ labels, float* __restrict__ out3)
{
    // smem: As/Bs fixed; colred / rowredf / rowredp alias As(+Bs) between phases.
    __shared__ __align__(16) unsigned char smraw[2 * 16 * 130 * 4 + 512];
    float (*As)[130] = reinterpret_cast<float(*)[130]>(smraw);
    float (*Bs)[130] = reinterpret_cast<float(*)[130]>(smraw + 16 * 130 * 4);
    float (*colred)[128] = reinterpret_cast<float(*)[128]>(smraw);        // 8 KB
    float (*rowredf)[16] = reinterpret_cast<float(*)[16]>(smraw);         // 8 KB
    ull   (*rowredp)[16] = reinterpret_cast<ull(*)[16]>(smraw);           // 16 KB
    int* slabel = reinterpret_cast<int*>(smraw + 2 * 16 * 130 * 4);

    const int tid = threadIdx.x;
    const int tx = tid & 15;        // col group (8 cols each)
    const int ty = tid >> 4;        // row group (8 rows each)
    const int rowbase = blockIdx.y * 128;
    const int colsplit0 = blockIdx.x * 1024;

    const float* sqa = (MODE == 1) ? (const float*)g_sqx : (const float*)g_sqc;
    const float* sqb = (const float*)g_sqc;

    if (MODE == 1 && tid < 128) {
        int r = rowbase + tid;
        slabel[tid] = g_lab32 ? ((const int*)labels)[r]
                              : (int)((const long long*)labels)[r];
    }

    float minv[8];
    int mincol[8];
#pragma unroll
    for (int i = 0; i < 8; i++) { minv[i] = 3.0e38f; mincol[i] = 0x7fffffff; }

    for (int chunk = 0; chunk < 8; chunk++) {
        const int colbase = colsplit0 + chunk * 128;
        ull acc2[8][4];
#pragma unroll
        for (int i = 0; i < 8; i++)
#pragma unroll
            for (int j = 0; j < 4; j++) acc2[i][j] = 0ull;   // (0.0f, 0.0f)

        for (int kt = 0; kt < DK; kt += 16) {
#pragma unroll
            for (int p = 0; p < 2; p++) {
                int idx = p * 256 + tid;
                int row = idx >> 2;
                int kq = (idx & 3) * 4;
                float4 va = *reinterpret_cast<const float4*>(
                    &A[(size_t)(rowbase + row) * DK + kt + kq]);
                As[kq + 0][row] = va.x; As[kq + 1][row] = va.y;
                As[kq + 2][row] = va.z; As[kq + 3][row] = va.w;
                float4 vb = *reinterpret_cast<const float4*>(
                    &Bm[(size_t)(colbase + row) * DK + kt + kq]);
                Bs[kq + 0][row] = vb.x; Bs[kq + 1][row] = vb.y;
                Bs[kq + 2][row] = vb.z; Bs[kq + 3][row] = vb.w;
            }
            __syncthreads();
#pragma unroll
            for (int k = 0; k < 16; k++) {
                ull b2[4];
#pragma unroll
                for (int j4 = 0; j4 < 4; j4++) {
                    float2 bb = *reinterpret_cast<const float2*>(&Bs[k][tx * 8 + j4 * 2]);
                    asm("mov.b64 %0, {%1, %2};" : "=l"(b2[j4]) : "f"(bb.x), "f"(bb.y));
                }
#pragma unroll
                for (int i = 0; i < 8; i++) {
                    float av = As[k][ty * 8 + i];
                    ull a2;
                    asm("mov.b64 %0, {%1, %1};" : "=l"(a2) : "f"(av));
#pragma unroll
                    for (int j4 = 0; j4 < 4; j4++)
                        asm("fma.rn.f32x2 %0, %1, %2, %0;"
                            : "+l"(acc2[i][j4]) : "l"(a2), "l"(b2[j4]));
                }
            }
            __syncthreads();
        }

        // -------- epilogue for this 128x128 chunk --------
        if (MODE == 1) {
#pragma unroll
            for (int i = 0; i < 8; i++) {
                int rl = ty * 8 + i;
                int r = rowbase + rl;
                float sa = sqa[r];
                int lbl = slabel[rl];
#pragma unroll
                for (int j4 = 0; j4 < 4; j4++) {
                    float p0 = __uint_as_float((unsigned)acc2[i][j4]);
                    float p1 = __uint_as_float((unsigned)(acc2[i][j4] >> 32));
                    int c0 = colbase + tx * 8 + j4 * 2;
                    float d0 = fminf(fmaxf(sa + sqb[c0] - 2.0f * p0, 1e-12f), 1e12f);
                    float d1 = fminf(fmaxf(sa + sqb[c0 + 1] - 2.0f * p1, 1e-12f), 1e12f);
                    if (c0 == lbl) g_dpos[r] = d0; else minv[i] = fminf(minv[i], d0);
                    if (c0 + 1 == lbl) g_dpos[r] = d1; else minv[i] = fminf(minv[i], d1);
                }
            }
        } else {
            float colpart[8];
#pragma unroll
            for (int j = 0; j < 8; j++) colpart[j] = 0.0f;
#pragma unroll
            for (int i = 0; i < 8; i++) {
                int r = rowbase + ty * 8 + i;
                float sa = sqa[r];
                float dv[8];
#pragma unroll
                for (int j4 = 0; j4 < 4; j4++) {
                    float p0 = __uint_as_float((unsigned)acc2[i][j4]);
                    float p1 = __uint_as_float((unsigned)(acc2[i][j4] >> 32));
                    int c0 = colbase + tx * 8 + j4 * 2;
                    dv[j4 * 2]     = fminf(fmaxf(sa + sqb[c0] - 2.0f * p0, 1e-12f), 1e12f);
                    dv[j4 * 2 + 1] = fminf(fmaxf(sa + sqb[c0 + 1] - 2.0f * p1, 1e-12f), 1e12f);
                }
#pragma unroll
                for (int j = 0; j < 8; j++) {
                    int c = colbase + tx * 8 + j;
                    colpart[j] += dv[j];
                    if (c != r && dv[j] < minv[i]) { minv[i] = dv[j]; mincol[i] = c; }
                }
                float2* op = reinterpret_cast<float2*>(
                    &out3[(size_t)r * CN + colbase + tx * 8]);
                op[0] = make_float2(dv[0], dv[1]);
                op[1] = make_float2(dv[2], dv[3]);
                op[2] = make_float2(dv[4], dv[5]);
                op[3] = make_float2(dv[6], dv[7]);
            }
            // column-sum reduce across the 16 row-groups (colred aliases As; safe
            // after the k-loop's trailing __syncthreads)
#pragma unroll
            for (int j = 0; j < 8; j++) colred[ty][tx * 8 + j] = colpart[j];
            __syncthreads();
            if (tid < 128) {
                float s = 0.0f;
#pragma unroll
                for (int t = 0; t < 16; t++) s += colred[t][tid];
                atomicAdd(&g_colsum[colbase + tid], s);
            }
            __syncthreads();
        }
    }

    // -------- final per-row reduction across the 16 col-groups --------
    if (MODE == 1) {
        __syncthreads();
#pragma unroll
        for (int i = 0; i < 8; i++) rowredf[ty * 8 + i][tx] = minv[i];
        __syncthreads();
        if (tid < 128) {
            float m = 3.0e38f;
#pragma unroll
            for (int t = 0; t < 16; t++) m = fminf(m, rowredf[tid][t]);
            atomicMin(&g_rowmin_bits[rowbase + tid], __float_as_uint(m));
        }
    } else {
        __syncthreads();
#pragma unroll
        for (int i = 0; i < 8; i++)
            rowredp[ty * 8 + i][tx] =
                ((ull)__float_as_uint(minv[i]) << 32) | (unsigned)mincol[i];
        __syncthreads();
        if (tid < 128) {
            ull m = 0xFFFFFFFFFFFFFFFFull;
#pragma unroll
            for (int t = 0; t < 16; t++) m = min(m, rowredp[tid][t]);
            atomicMin(&g_rowpack[rowbase + tid], m);
        }
    }
}

// ---------------- finalize ---------------------------------------------------
__global__ void finalize_kernel(float* __restrict__ out) {
    __shared__ double red[256];
    int tid = threadIdx.x;

    double s = 0.0;
    for (int i = tid; i < BN; i += 256) {
        float dn = __uint_as_float(g_rowmin_bits[i]);
        s += (double)(g_dpos[i] / (dn + 1.0f));
    }
    red[tid] = s; __syncthreads();
    for (int o = 128; o > 0; o >>= 1) {
        if (tid < o) red[tid] += red[tid + o];
        __syncthreads();
    }
    if (tid == 0) out[0] = (float)(red[0] / (double)BN);
    __syncthreads();

    s = 0.0;
    for (int c = tid; c < CN; c += 256) {
        unsigned j = (unsigned)(g_rowpack[c] & 0xFFFFFFFFull);
        s += (double)g_colsum[j];
    }
    red[tid] = s; __syncthreads();
    for (int o = 128; o > 0; o >>= 1) {
        if (tid < o) red[tid] += red[tid + o];
        __syncthreads();
    }
    if (tid == 0) out[1] = (float)(-red[0] / ((double)CN * (double)CN));
}

// ---------------- launch -----------------------------------------------------
extern "C" void kernel_launch(void* const* d_in, const int* in_sizes, int n_in,
                              void* d_out, int out_size) {
    const float* x = (const float*)d_in[0];
    const void* labels = d_in[1];
    const float* centers = (const float*)d_in[2];
    float* out = (float*)d_out;
    float* out3 = out + 2;   // [loss_cent, loss_dis3, distmat3(8192x8192)]

    init_kernel<<<(CN + 255) / 256, 256>>>();
    detect_kernel<<<(BN / 2 + 255) / 256, 256>>>((const unsigned*)labels);
    sqnorm_kernel<<<BN / 8, 256>>>(x, BN, 0);
    sqnorm_kernel<<<CN / 8, 256>>>(centers, CN, 1);

    dim3 grid(8, 64);   // (col-splits, row-blocks)
    distmat_kernel<1><<<grid, 256>>>(x, centers, labels, nullptr);
    distmat_kernel<2><<<grid, 256>>>(centers, centers, nullptr, out3);

    finalize_kernel<<<1, 256>>>(out);
}

// round 3
// speedup vs baseline: 2.9728x; 2.9728x over previous
#include <cuda_runtime.h>
#include <cstdint>

#define BN 8192
#define CN 8192
#define DK 256
#define KC 32
#define NCH (DK / KC)
#define LDA 36                      // smem row stride in floats (pad 32 -> 36)
#define STAGE_B (128 * LDA * 4)     // 18432 bytes per A/B stage

typedef unsigned long long ull;

// ---------------- scratch ----------------------------------------------------
__device__ float g_sqx[BN];
__device__ float g_sqc[CN];
__device__ float g_colsum[CN];
__device__ unsigned g_rowmin_bits[BN];
__device__ ull g_rowpack[CN];
__device__ float g_dpos[BN];
__device__ int g_lab32;

__device__ __forceinline__ uint32_t s2u(const void* p) {
    uint32_t a;
    asm("{ .reg .u64 t; cvta.to.shared.u64 t, %1; cvt.u32.u64 %0, t; }" : "=r"(a) : "l"(p));
    return a;
}
__device__ __forceinline__ void cp16(uint32_t dst, const void* src) {
    asm volatile("cp.async.cg.shared.global [%0], [%1], 16;" :: "r"(dst), "l"(src));
}

// ---------------- init / detect / sqnorm -------------------------------------
__global__ void init_kernel() {
    int i = blockIdx.x * blockDim.x + threadIdx.x;
    if (i < CN) {
        g_colsum[i] = 0.0f;
        g_rowmin_bits[i] = 0x7F7FFFFFu;
        g_rowpack[i] = 0xFFFFFFFFFFFFFFFFull;
    }
    if (i == 0) g_lab32 = 0;
}

__global__ void detect_kernel(const unsigned* __restrict__ lw) {
    int i = blockIdx.x * blockDim.x + threadIdx.x;
    if (i < BN / 2) {
        if (lw[2 * i + 1] != 0u) g_lab32 = 1;
    }
}

__global__ void sqnorm_kernel(const float* __restrict__ X, int nrows, int which) {
    int warp = (blockIdx.x * blockDim.x + threadIdx.x) >> 5;
    int lane = threadIdx.x & 31;
    if (warp >= nrows) return;
    const float4* p = reinterpret_cast<const float4*>(X + (size_t)warp * DK);
    float s = 0.0f;
#pragma unroll
    for (int q = 0; q < 2; q++) {
        float4 v = p[lane * 2 + q];
        s += v.x * v.x + v.y * v.y + v.z * v.z + v.w * v.w;
    }
#pragma unroll
    for (int o = 16; o; o >>= 1) s += __shfl_xor_sync(0xffffffffu, s, o);
    if (lane == 0) {
        if (which == 0) g_sqx[warp] = s; else g_sqc[warp] = s;
    }
}

// ---------------- tf32 mma.sync fused distance GEMM ---------------------------
// CTA tile 128x128, 8 warps (2m x 4n), warp tile 64x32.
// MODE 1: dist(x, centers) -> d_pos + min_{c != label} (nothing stored)
// MODE 2: dist(centers, centers) -> store tile + argmin_{c != r}
template <int MODE>
__global__ void __launch_bounds__(256, 2) distmat_mma(
    const float* __restrict__ A, const float* __restrict__ Bm,
    const void* __restrict__ labels, float* __restrict__ out3)
{
    extern __shared__ __align__(16) char smem[];
    const uint32_t smA0 = s2u(smem);
    const uint32_t smB0 = smA0 + 2 * STAGE_B;
    const int tid = threadIdx.x;
    const int wid = tid >> 5;
    const int lane = tid & 31;
    const int g = lane >> 2;        // group id (row within fragment)
    const int t = lane & 3;         // thread in group
    const int warp_m = wid >> 2;    // 0..1
    const int warp_n = wid & 3;     // 0..3
    const int mrow0 = blockIdx.y * 128;
    const int ncol0 = blockIdx.x * 128;

    // ---- async load helper (one chunk into stage s) ----
    const int r_ld = tid >> 3;            // 0..31 per pass (4 passes => 128 rows)
    const int q_ld = tid & 7;             // float4 index within 32-float row
    const float* Abase = A + (size_t)(mrow0 + r_ld) * DK + q_ld * 4;
    const float* Bbase = Bm + (size_t)(ncol0 + r_ld) * DK + q_ld * 4;
    const uint32_t dstAoff = r_ld * (LDA * 4) + q_ld * 16;
    const uint32_t dstBoff = dstAoff;

#define ISSUE_CHUNK(c, s)                                                      \
    {                                                                          \
        _Pragma("unroll")                                                      \
        for (int it = 0; it < 4; it++) {                                       \
            cp16(smA0 + (s) * STAGE_B + dstAoff + it * 32 * (LDA * 4),         \
                 Abase + (size_t)it * 32 * DK + (c) * KC);                     \
            cp16(smB0 + (s) * STAGE_B + dstBoff + it * 32 * (LDA * 4),         \
                 Bbase + (size_t)it * 32 * DK + (c) * KC);                     \
        }                                                                      \
        asm volatile("cp.async.commit_group;");                                \
    }

    float acc[4][4][4];
#pragma unroll
    for (int i = 0; i < 4; i++)
#pragma unroll
        for (int j = 0; j < 4; j++)
#pragma unroll
            for (int u = 0; u < 4; u++) acc[i][j][u] = 0.0f;

    ISSUE_CHUNK(0, 0);
    ISSUE_CHUNK(1, 1);

    // fragment smem addresses (byte offsets within a stage)
    const uint32_t aRow = warp_m * 64 + g;           // + mt*16 (+8)
    const uint32_t bRow = warp_n * 32 + g;           // + nt*8

    for (int c = 0; c < NCH; c++) {
        const int s = c & 1;
        if (c == NCH - 1) asm volatile("cp.async.wait_group 0;");
        else              asm volatile("cp.async.wait_group 1;");
        __syncthreads();

        const uint32_t aBase = smA0 + s * STAGE_B;
        const uint32_t bBase = smB0 + s * STAGE_B;
#pragma unroll
        for (int ks = 0; ks < 4; ks++) {
            const int k0 = ks * 8 + t;
            uint32_t af[4][4], bf[4][2];
#pragma unroll
            for (int mt = 0; mt < 4; mt++) {
                uint32_t base = aBase + ((aRow + mt * 16) * LDA + k0) * 4;
                asm volatile("ld.shared.b32 %0, [%1];" : "=r"(af[mt][0]) : "r"(base));
                asm volatile("ld.shared.b32 %0, [%1];" : "=r"(af[mt][1]) : "r"(base + 8 * LDA * 4));
                asm volatile("ld.shared.b32 %0, [%1];" : "=r"(af[mt][2]) : "r"(base + 16));
                asm volatile("ld.shared.b32 %0, [%1];" : "=r"(af[mt][3]) : "r"(base + 8 * LDA * 4 + 16));
            }
#pragma unroll
            for (int nt = 0; nt < 4; nt++) {
                uint32_t base = bBase + ((bRow + nt * 8) * LDA + k0) * 4;
                asm volatile("ld.shared.b32 %0, [%1];" : "=r"(bf[nt][0]) : "r"(base));
                asm volatile("ld.shared.b32 %0, [%1];" : "=r"(bf[nt][1]) : "r"(base + 16));
            }
#pragma unroll
            for (int mt = 0; mt < 4; mt++)
#pragma unroll
                for (int nt = 0; nt < 4; nt++)
                    asm volatile(
                        "mma.sync.aligned.m16n8k8.row.col.f32.tf32.tf32.f32 "
                        "{%0,%1,%2,%3}, {%4,%5,%6,%7}, {%8,%9}, {%0,%1,%2,%3};"
                        : "+f"(acc[mt][nt][0]), "+f"(acc[mt][nt][1]),
                          "+f"(acc[mt][nt][2]), "+f"(acc[mt][nt][3])
                        : "r"(af[mt][0]), "r"(af[mt][1]), "r"(af[mt][2]), "r"(af[mt][3]),
                          "r"(bf[nt][0]), "r"(bf[nt][1]));
        }
        __syncthreads();
        if (c + 2 < NCH) ISSUE_CHUNK(c + 2, s);
    }

    // ---------------- epilogue ----------------
    const float* sqa = (MODE == 1) ? (const float*)g_sqx : (const float*)g_sqc;
    float sarow[8];
    int lbl[8];
#pragma unroll
    for (int mt = 0; mt < 4; mt++)
#pragma unroll
        for (int h = 0; h < 2; h++) {
            int r = mrow0 + warp_m * 64 + mt * 16 + h * 8 + g;
            sarow[mt * 2 + h] = sqa[r];
            if (MODE == 1)
                lbl[mt * 2 + h] = g_lab32 ? ((const int*)labels)[r]
                                          : (int)((const long long*)labels)[r];
        }
    float sbcol[8];
#pragma unroll
    for (int nt = 0; nt < 4; nt++) {
        int c0 = ncol0 + warp_n * 32 + nt * 8 + t * 2;
        sbcol[nt * 2] = g_sqc[c0];
        sbcol[nt * 2 + 1] = g_sqc[c0 + 1];
    }

    float minv[8];
    int minc[8];
#pragma unroll
    for (int i = 0; i < 8; i++) { minv[i] = 3.0e38f; minc[i] = 0x7fffffff; }

#pragma unroll
    for (int mt = 0; mt < 4; mt++)
#pragma unroll
        for (int h = 0; h < 2; h++) {
            const int ri = mt * 2 + h;
            const int r = mrow0 + warp_m * 64 + mt * 16 + h * 8 + g;
            const float sa = sarow[ri];
#pragma unroll
            for (int nt = 0; nt < 4; nt++) {
                const int c0 = ncol0 + warp_n * 32 + nt * 8 + t * 2;
                float p0 = acc[mt][nt][h * 2];
                float p1 = acc[mt][nt][h * 2 + 1];
                float d0 = fminf(fmaxf(fmaf(-2.0f, p0, sa + sbcol[nt * 2]), 1e-12f), 1e12f);
                float d1 = fminf(fmaxf(fmaf(-2.0f, p1, sa + sbcol[nt * 2 + 1]), 1e-12f), 1e12f);
                if (MODE == 1) {
                    if (c0 == lbl[ri]) g_dpos[r] = d0;
                    else minv[ri] = fminf(minv[ri], d0);
                    if (c0 + 1 == lbl[ri]) g_dpos[r] = d1;
                    else minv[ri] = fminf(minv[ri], d1);
                } else {
                    if (c0 != r && d0 < minv[ri]) { minv[ri] = d0; minc[ri] = c0; }
                    if (c0 + 1 != r && d1 < minv[ri]) { minv[ri] = d1; minc[ri] = c0 + 1; }
                    *(float2*)(out3 + (size_t)r * CN + c0) = make_float2(d0, d1);
                }
            }
        }

    // cross-thread per-row reduction: 16 threads own each row (4 lanes x 4 n-warps)
    __syncthreads();
    if (MODE == 1) {
        float* red = (float*)smem;   // 128 x 16 floats = 8 KB
#pragma unroll
        for (int mt = 0; mt < 4; mt++)
#pragma unroll
            for (int h = 0; h < 2; h++) {
                int rl = warp_m * 64 + mt * 16 + h * 8 + g;
                red[rl * 16 + warp_n * 4 + t] = minv[mt * 2 + h];
            }
        __syncthreads();
        if (tid < 128) {
            float m = 3.0e38f;
#pragma unroll
            for (int i = 0; i < 16; i++) m = fminf(m, red[tid * 16 + i]);
            atomicMin(&g_rowmin_bits[mrow0 + tid], __float_as_uint(m));
        }
    } else {
        ull* red = (ull*)smem;       // 128 x 16 x 8B = 16 KB
#pragma unroll
        for (int mt = 0; mt < 4; mt++)
#pragma unroll
            for (int h = 0; h < 2; h++) {
                int rl = warp_m * 64 + mt * 16 + h * 8 + g;
                red[rl * 16 + warp_n * 4 + t] =
                    ((ull)__float_as_uint(minv[mt * 2 + h]) << 32) |
                    (unsigned)minc[mt * 2 + h];
            }
        __syncthreads();
        if (tid < 128) {
            ull m = 0xFFFFFFFFFFFFFFFFull;
#pragma unroll
            for (int i = 0; i < 16; i++) m = min(m, red[tid * 16 + i]);
            atomicMin(&g_rowpack[mrow0 + tid], m);
        }
    }
#undef ISSUE_CHUNK
}

// ---------------- column sums of distmat3 -------------------------------------
__global__ void colsum_kernel(const float* __restrict__ out3) {
    __shared__ float red[256];
    int tid = threadIdx.x;
    int col = blockIdx.x * 128 + (tid & 127);
    int rhalf = tid >> 7;
    float s = 0.0f;
    int r0 = blockIdx.y * 1024;
    for (int r = r0 + rhalf; r < r0 + 1024; r += 2)
        s += out3[(size_t)r * CN + col];
    red[tid] = s;
    __syncthreads();
    if (tid < 128) atomicAdd(&g_colsum[col], red[tid] + red[tid + 128]);
}

// ---------------- finalize ----------------------------------------------------
__global__ void finalize_kernel(float* __restrict__ out) {
    __shared__ double red[256];
    int tid = threadIdx.x;

    double s = 0.0;
    for (int i = tid; i < BN; i += 256) {
        float dn = __uint_as_float(g_rowmin_bits[i]);
        s += (double)(g_dpos[i] / (dn + 1.0f));
    }
    red[tid] = s; __syncthreads();
    for (int o = 128; o > 0; o >>= 1) {
        if (tid < o) red[tid] += red[tid + o];
        __syncthreads();
    }
    if (tid == 0) out[0] = (float)(red[0] / (double)BN);
    __syncthreads();

    s = 0.0;
    for (int c = tid; c < CN; c += 256) {
        unsigned j = (unsigned)(g_rowpack[c] & 0xFFFFFFFFull);
        s += (double)g_colsum[j];
    }
    red[tid] = s; __syncthreads();
    for (int o = 128; o > 0; o >>= 1) {
        if (tid < o) red[tid] += red[tid + o];
        __syncthreads();
    }
    if (tid == 0) out[1] = (float)(-red[0] / ((double)CN * (double)CN));
}

// ---------------- launch -------------------------------------------------------
#define SMEM_BYTES (4 * STAGE_B)

extern "C" void kernel_launch(void* const* d_in, const int* in_sizes, int n_in,
                              void* d_out, int out_size) {
    const float* x = (const float*)d_in[0];
    const void* labels = d_in[1];
    const float* centers = (const float*)d_in[2];
    float* out = (float*)d_out;
    float* out3 = out + 2;

    cudaFuncSetAttribute(distmat_mma<1>, cudaFuncAttributeMaxDynamicSharedMemorySize, SMEM_BYTES);
    cudaFuncSetAttribute(distmat_mma<2>, cudaFuncAttributeMaxDynamicSharedMemorySize, SMEM_BYTES);

    init_kernel<<<(CN + 255) / 256, 256>>>();
    detect_kernel<<<(BN / 2 + 255) / 256, 256>>>((const unsigned*)labels);
    sqnorm_kernel<<<BN / 8, 256>>>(x, BN, 0);
    sqnorm_kernel<<<CN / 8, 256>>>(centers, CN, 1);

    dim3 grid(CN / 128, BN / 128);   // 64 x 64
    distmat_mma<1><<<grid, 256, SMEM_BYTES>>>(x, centers, labels, nullptr);
    distmat_mma<2><<<grid, 256, SMEM_BYTES>>>(centers, centers, nullptr, out3);

    colsum_kernel<<<dim3(CN / 128, 8), 256>>>(out3);
    finalize_kernel<<<1, 256>>>(out);
}

// round 4
// speedup vs baseline: 3.0956x; 1.0413x over previous
#include <cuda_runtime.h>
#include <cstdint>

#define BN 8192
#define CN 8192
#define DK 256
#define KC 16
#define NCH (DK / KC)         // 16 chunks
#define LDW 20                // smem row stride in floats (16 + 4 pad)
#define STAGE_B (128 * LDW * 4)   // 10240 bytes per A/B stage
#define NSTAGE 4

typedef unsigned long long ull;

// ---------------- scratch ----------------------------------------------------
__device__ float g_sqx[BN];
__device__ float g_sqc[CN];
__device__ float g_colsum[CN];
__device__ unsigned g_rowmin_bits[BN];
__device__ ull g_rowpack[CN];
__device__ float g_dpos[BN];
__device__ int g_lab32;

__device__ __forceinline__ uint32_t s2u(const void* p) {
    uint32_t a;
    asm("{ .reg .u64 t; cvta.to.shared.u64 t, %1; cvt.u32.u64 %0, t; }" : "=r"(a) : "l"(p));
    return a;
}
__device__ __forceinline__ void cp16(uint32_t dst, const void* src) {
    asm volatile("cp.async.cg.shared.global [%0], [%1], 16;" :: "r"(dst), "l"(src));
}

// ---------------- init / detect / sqnorm -------------------------------------
__global__ void init_kernel() {
    int i = blockIdx.x * blockDim.x + threadIdx.x;
    if (i < CN) {
        g_colsum[i] = 0.0f;
        g_rowmin_bits[i] = 0x7F7FFFFFu;
        g_rowpack[i] = 0xFFFFFFFFFFFFFFFFull;
    }
    if (i == 0) g_lab32 = 0;
}

__global__ void detect_kernel(const unsigned* __restrict__ lw) {
    int i = blockIdx.x * blockDim.x + threadIdx.x;
    if (i < BN / 2) {
        if (lw[2 * i + 1] != 0u) g_lab32 = 1;
    }
}

__global__ void sqnorm_kernel(const float* __restrict__ X, int nrows, int which) {
    int warp = (blockIdx.x * blockDim.x + threadIdx.x) >> 5;
    int lane = threadIdx.x & 31;
    if (warp >= nrows) return;
    const float4* p = reinterpret_cast<const float4*>(X + (size_t)warp * DK);
    float s = 0.0f;
#pragma unroll
    for (int q = 0; q < 2; q++) {
        float4 v = p[lane * 2 + q];
        s += v.x * v.x + v.y * v.y + v.z * v.z + v.w * v.w;
    }
#pragma unroll
    for (int o = 16; o; o >>= 1) s += __shfl_xor_sync(0xffffffffu, s, o);
    if (lane == 0) {
        if (which == 0) g_sqx[warp] = s; else g_sqc[warp] = s;
    }
}

// ---------------- tf32 mma.sync fused distance GEMM ---------------------------
// CTA tile 128x128, 8 warps (2m x 4n), warp tile 64x32. 4-stage cp.async pipe.
// MODE 1: dist(x, centers) -> d_pos + min_{c != label}
// MODE 2: dist(centers, centers) -> store tile + argmin_{c != r} + fused colsum
template <int MODE>
__global__ void __launch_bounds__(256, 2) distmat_mma(
    const float* __restrict__ A, const float* __restrict__ Bm,
    const void* __restrict__ labels, float* __restrict__ out3)
{
    extern __shared__ __align__(16) char smem[];
    const uint32_t smA0 = s2u(smem);
    const uint32_t smB0 = smA0 + NSTAGE * STAGE_B;
    const int tid = threadIdx.x;
    const int wid = tid >> 5;
    const int lane = tid & 31;
    const int g = lane >> 2;
    const int t = lane & 3;
    const int warp_m = wid >> 2;    // 0..1
    const int warp_n = wid & 3;     // 0..3
    const int mrow0 = blockIdx.y * 128;
    const int ncol0 = blockIdx.x * 128;

    // loader mapping: idx = it*256+tid, row = idx>>2 (0..127), q = idx&3
    const int r_ld = tid >> 2;            // 0..63 (2 passes => 128 rows)
    const int q_ld = tid & 3;
    const float* Abase = A + (size_t)(mrow0 + r_ld) * DK + q_ld * 4;
    const float* Bbase = Bm + (size_t)(ncol0 + r_ld) * DK + q_ld * 4;
    const uint32_t dstOff = r_ld * (LDW * 4) + q_ld * 16;

#define ISSUE_CHUNK(c)                                                         \
    {                                                                          \
        const int s_ = (c) & (NSTAGE - 1);                                     \
        _Pragma("unroll")                                                      \
        for (int it = 0; it < 2; it++) {                                       \
            cp16(smA0 + s_ * STAGE_B + dstOff + it * 64 * (LDW * 4),           \
                 Abase + (size_t)it * 64 * DK + (c) * KC);                     \
            cp16(smB0 + s_ * STAGE_B + dstOff + it * 64 * (LDW * 4),           \
                 Bbase + (size_t)it * 64 * DK + (c) * KC);                     \
        }                                                                      \
        asm volatile("cp.async.commit_group;");                                \
    }

    float acc[4][4][4];
#pragma unroll
    for (int i = 0; i < 4; i++)
#pragma unroll
        for (int j = 0; j < 4; j++)
#pragma unroll
            for (int u = 0; u < 4; u++) acc[i][j][u] = 0.0f;

    ISSUE_CHUNK(0); ISSUE_CHUNK(1); ISSUE_CHUNK(2);

    const uint32_t aRow = warp_m * 64 + g;
    const uint32_t bRow = warp_n * 32 + g;

    for (int c = 0; c < NCH; c++) {
        // ensure chunk c is complete: allow min(2, NCH-1-c) newer groups pending
        if (c < NCH - 2)      asm volatile("cp.async.wait_group 2;");
        else if (c == NCH - 2) asm volatile("cp.async.wait_group 1;");
        else                   asm volatile("cp.async.wait_group 0;");
        __syncthreads();
        if (c + 3 < NCH) ISSUE_CHUNK(c + 3);

        const int s = c & (NSTAGE - 1);
        const uint32_t aBase = smA0 + s * STAGE_B;
        const uint32_t bBase = smB0 + s * STAGE_B;
#pragma unroll
        for (int ks = 0; ks < 2; ks++) {
            const int k0 = ks * 8 + t;
            uint32_t af[4][4], bf[4][2];
#pragma unroll
            for (int mt = 0; mt < 4; mt++) {
                uint32_t base = aBase + ((aRow + mt * 16) * LDW + k0) * 4;
                asm volatile("ld.shared.b32 %0, [%1];" : "=r"(af[mt][0]) : "r"(base));
                asm volatile("ld.shared.b32 %0, [%1];" : "=r"(af[mt][1]) : "r"(base + 8 * LDW * 4));
                asm volatile("ld.shared.b32 %0, [%1];" : "=r"(af[mt][2]) : "r"(base + 16));
                asm volatile("ld.shared.b32 %0, [%1];" : "=r"(af[mt][3]) : "r"(base + 8 * LDW * 4 + 16));
            }
#pragma unroll
            for (int nt = 0; nt < 4; nt++) {
                uint32_t base = bBase + ((bRow + nt * 8) * LDW + k0) * 4;
                asm volatile("ld.shared.b32 %0, [%1];" : "=r"(bf[nt][0]) : "r"(base));
                asm volatile("ld.shared.b32 %0, [%1];" : "=r"(bf[nt][1]) : "r"(base + 16));
            }
#pragma unroll
            for (int mt = 0; mt < 4; mt++)
#pragma unroll
                for (int nt = 0; nt < 4; nt++)
                    asm volatile(
                        "mma.sync.aligned.m16n8k8.row.col.f32.tf32.tf32.f32 "
                        "{%0,%1,%2,%3}, {%4,%5,%6,%7}, {%8,%9}, {%0,%1,%2,%3};"
                        : "+f"(acc[mt][nt][0]), "+f"(acc[mt][nt][1]),
                          "+f"(acc[mt][nt][2]), "+f"(acc[mt][nt][3])
                        : "r"(af[mt][0]), "r"(af[mt][1]), "r"(af[mt][2]), "r"(af[mt][3]),
                          "r"(bf[nt][0]), "r"(bf[nt][1]));
        }
    }

    // ---------------- epilogue ----------------
    const float* sqa = (MODE == 1) ? (const float*)g_sqx : (const float*)g_sqc;
    float sarow[8];
    int lbl[8];
#pragma unroll
    for (int mt = 0; mt < 4; mt++)
#pragma unroll
        for (int h = 0; h < 2; h++) {
            int r = mrow0 + warp_m * 64 + mt * 16 + h * 8 + g;
            sarow[mt * 2 + h] = sqa[r];
            if (MODE == 1)
                lbl[mt * 2 + h] = g_lab32 ? ((const int*)labels)[r]
                                          : (int)((const long long*)labels)[r];
        }
    float sbcol[8];
#pragma unroll
    for (int nt = 0; nt < 4; nt++) {
        int c0 = ncol0 + warp_n * 32 + nt * 8 + t * 2;
        sbcol[nt * 2] = g_sqc[c0];
        sbcol[nt * 2 + 1] = g_sqc[c0 + 1];
    }

    float minv[8];
    int minc[8];
    float colpart[8];
#pragma unroll
    for (int i = 0; i < 8; i++) { minv[i] = 3.0e38f; minc[i] = 0x7fffffff; colpart[i] = 0.0f; }

#pragma unroll
    for (int mt = 0; mt < 4; mt++)
#pragma unroll
        for (int h = 0; h < 2; h++) {
            const int ri = mt * 2 + h;
            const int r = mrow0 + warp_m * 64 + mt * 16 + h * 8 + g;
            const float sa = sarow[ri];
#pragma unroll
            for (int nt = 0; nt < 4; nt++) {
                const int c0 = ncol0 + warp_n * 32 + nt * 8 + t * 2;
                float p0 = acc[mt][nt][h * 2];
                float p1 = acc[mt][nt][h * 2 + 1];
                float d0 = fminf(fmaxf(fmaf(-2.0f, p0, sa + sbcol[nt * 2]), 1e-12f), 1e12f);
                float d1 = fminf(fmaxf(fmaf(-2.0f, p1, sa + sbcol[nt * 2 + 1]), 1e-12f), 1e12f);
                if (MODE == 1) {
                    if (c0 == lbl[ri]) g_dpos[r] = d0;
                    else minv[ri] = fminf(minv[ri], d0);
                    if (c0 + 1 == lbl[ri]) g_dpos[r] = d1;
                    else minv[ri] = fminf(minv[ri], d1);
                } else {
                    if (c0 != r && d0 < minv[ri]) { minv[ri] = d0; minc[ri] = c0; }
                    if (c0 + 1 != r && d1 < minv[ri]) { minv[ri] = d1; minc[ri] = c0 + 1; }
                    colpart[nt * 2] += d0;
                    colpart[nt * 2 + 1] += d1;
                    *(float2*)(out3 + (size_t)r * CN + c0) = make_float2(d0, d1);
                }
            }
        }

    // fused column sums (MODE 2): butterfly over the 8 g-lanes, then REDG
    if (MODE == 2) {
#pragma unroll
        for (int j = 0; j < 8; j++) {
            colpart[j] += __shfl_xor_sync(0xffffffffu, colpart[j], 4);
            colpart[j] += __shfl_xor_sync(0xffffffffu, colpart[j], 8);
            colpart[j] += __shfl_xor_sync(0xffffffffu, colpart[j], 16);
        }
        if (g == 0) {
#pragma unroll
            for (int nt = 0; nt < 4; nt++) {
                int c0 = ncol0 + warp_n * 32 + nt * 8 + t * 2;
                atomicAdd(&g_colsum[c0], colpart[nt * 2]);
                atomicAdd(&g_colsum[c0 + 1], colpart[nt * 2 + 1]);
            }
        }
    }

    // cross-thread per-row reduction: 16 threads own each row
    __syncthreads();
    if (MODE == 1) {
        float* red = (float*)smem;
#pragma unroll
        for (int mt = 0; mt < 4; mt++)
#pragma unroll
            for (int h = 0; h < 2; h++) {
                int rl = warp_m * 64 + mt * 16 + h * 8 + g;
                red[rl * 16 + warp_n * 4 + t] = minv[mt * 2 + h];
            }
        __syncthreads();
        if (tid < 128) {
            float m = 3.0e38f;
#pragma unroll
            for (int i = 0; i < 16; i++) m = fminf(m, red[tid * 16 + i]);
            atomicMin(&g_rowmin_bits[mrow0 + tid], __float_as_uint(m));
        }
    } else {
        ull* red = (ull*)smem;
#pragma unroll
        for (int mt = 0; mt < 4; mt++)
#pragma unroll
            for (int h = 0; h < 2; h++) {
                int rl = warp_m * 64 + mt * 16 + h * 8 + g;
                red[rl * 16 + warp_n * 4 + t] =
                    ((ull)__float_as_uint(minv[mt * 2 + h]) << 32) |
                    (unsigned)minc[mt * 2 + h];
            }
        __syncthreads();
        if (tid < 128) {
            ull m = 0xFFFFFFFFFFFFFFFFull;
#pragma unroll
            for (int i = 0; i < 16; i++) m = min(m, red[tid * 16 + i]);
            atomicMin(&g_rowpack[mrow0 + tid], m);
        }
    }
#undef ISSUE_CHUNK
}

// ---------------- finalize ----------------------------------------------------
__global__ void finalize_kernel(float* __restrict__ out) {
    __shared__ double red[256];
    int tid = threadIdx.x;

    double s = 0.0;
    for (int i = tid; i < BN; i += 256) {
        float dn = __uint_as_float(g_rowmin_bits[i]);
        s += (double)(g_dpos[i] / (dn + 1.0f));
    }
    red[tid] = s; __syncthreads();
    for (int o = 128; o > 0; o >>= 1) {
        if (tid < o) red[tid] += red[tid + o];
        __syncthreads();
    }
    if (tid == 0) out[0] = (float)(red[0] / (double)BN);
    __syncthreads();

    s = 0.0;
    for (int c = tid; c < CN; c += 256) {
        unsigned j = (unsigned)(g_rowpack[c] & 0xFFFFFFFFull);
        s += (double)g_colsum[j];
    }
    red[tid] = s; __syncthreads();
    for (int o = 128; o > 0; o >>= 1) {
        if (tid < o) red[tid] += red[tid + o];
        __syncthreads();
    }
    if (tid == 0) out[1] = (float)(-red[0] / ((double)CN * (double)CN));
}

// ---------------- launch -------------------------------------------------------
#define SMEM_BYTES (2 * NSTAGE * STAGE_B)    // 81920

extern "C" void kernel_launch(void* const* d_in, const int* in_sizes, int n_in,
                              void* d_out, int out_size) {
    const float* x = (const float*)d_in[0];
    const void* labels = d_in[1];
    const float* centers = (const float*)d_in[2];
    float* out = (float*)d_out;
    float* out3 = out + 2;

    cudaFuncSetAttribute(distmat_mma<1>, cudaFuncAttributeMaxDynamicSharedMemorySize, SMEM_BYTES);
    cudaFuncSetAttribute(distmat_mma<2>, cudaFuncAttributeMaxDynamicSharedMemorySize, SMEM_BYTES);

    init_kernel<<<(CN + 255) / 256, 256>>>();
    detect_kernel<<<(BN / 2 + 255) / 256, 256>>>((const unsigned*)labels);
    sqnorm_kernel<<<BN / 8, 256>>>(x, BN, 0);
    sqnorm_kernel<<<CN / 8, 256>>>(centers, CN, 1);

    dim3 grid(CN / 128, BN / 128);   // 64 x 64
    distmat_mma<1><<<grid, 256, SMEM_BYTES>>>(x, centers, labels, nullptr);
    distmat_mma<2><<<grid, 256, SMEM_BYTES>>>(centers, centers, nullptr, out3);

    finalize_kernel<<<1, 256>>>(out);
}

// round 6
// speedup vs baseline: 3.5374x; 1.1427x over previous
#include <cuda_runtime.h>
#include <cstdint>

#define BN 8192
#define CN 8192
#define DK 256
#define KC 16
#define NCH (DK / KC)             // 16 chunks
#define LDW 20                    // smem row stride in floats
#define STAGE_B (128 * LDW * 4)   // 10240 B per A/B stage
#define NSTAGE 4
#define LDT 132                   // transpose smem stride (floats)

typedef unsigned long long ull;

// ---------------- scratch ----------------------------------------------------
__device__ float g_sqx[BN];
__device__ float g_sqc[CN];
__device__ float g_colsum[CN];
__device__ unsigned g_rowmin_bits[BN];
__device__ ull g_rowpack[CN];
__device__ float g_dpos[BN];
__device__ int g_lab32;

__device__ __forceinline__ uint32_t s2u(const void* p) {
    uint32_t a;
    asm("{ .reg .u64 t; cvta.to.shared.u64 t, %1; cvt.u32.u64 %0, t; }" : "=r"(a) : "l"(p));
    return a;
}
__device__ __forceinline__ void cp16(uint32_t dst, const void* src) {
    asm volatile("cp.async.cg.shared.global [%0], [%1], 16;" :: "r"(dst), "l"(src));
}

// ---------------- init / detect / sqnorm -------------------------------------
__global__ void init_kernel() {
    int i = blockIdx.x * blockDim.x + threadIdx.x;
    if (i < CN) {
        g_colsum[i] = 0.0f;
        g_rowmin_bits[i] = 0x7F7FFFFFu;
        g_rowpack[i] = 0xFFFFFFFFFFFFFFFFull;
    }
    if (i == 0) g_lab32 = 0;
}

__global__ void detect_kernel(const unsigned* __restrict__ lw) {
    int i = blockIdx.x * blockDim.x + threadIdx.x;
    if (i < BN / 2) {
        if (lw[2 * i + 1] != 0u) g_lab32 = 1;
    }
}

__global__ void sqnorm_kernel(const float* __restrict__ X, int nrows, int which) {
    int warp = (blockIdx.x * blockDim.x + threadIdx.x) >> 5;
    int lane = threadIdx.x & 31;
    if (warp >= nrows) return;
    const float4* p = reinterpret_cast<const float4*>(X + (size_t)warp * DK);
    float s = 0.0f;
#pragma unroll
    for (int q = 0; q < 2; q++) {
        float4 v = p[lane * 2 + q];
        s += v.x * v.x + v.y * v.y + v.z * v.z + v.w * v.w;
    }
#pragma unroll
    for (int o = 16; o; o >>= 1) s += __shfl_xor_sync(0xffffffffu, s, o);
    if (lane == 0) {
        if (which == 0) g_sqx[warp] = s; else g_sqc[warp] = s;
    }
}

// ---------------- tf32 mma.sync fused distance GEMM ---------------------------
// MODE 1: dist(x, centers), grid (64, 64): d_pos + min_{c != label}.
// MODE 2: dist(centers, centers), triangular grid (2080): computes by <= bx
//         tiles only; mirrors off-diag tiles via smem transpose (float2 stores:
//         out3 base is only 8B-aligned!); row+col stats by symmetry.
template <int MODE>
__global__ void __launch_bounds__(256, 2) distmat_mma(
    const float* __restrict__ A, const float* __restrict__ Bm,
    const void* __restrict__ labels, float* __restrict__ out3)
{
    extern __shared__ __align__(16) char smem[];
    const uint32_t smA0 = s2u(smem);
    const uint32_t smB0 = smA0 + NSTAGE * STAGE_B;
    const int tid = threadIdx.x;
    const int wid = tid >> 5;
    const int lane = tid & 31;
    const int g = lane >> 2;
    const int t = lane & 3;
    const int warp_m = wid >> 2;
    const int warp_n = wid & 3;

    int bx, by;
    if (MODE == 1) {
        bx = blockIdx.x; by = blockIdx.y;
    } else {
        int k = blockIdx.x;
        bx = (int)((sqrtf(8.0f * (float)k + 1.0f) - 1.0f) * 0.5f);
        while ((bx + 1) * (bx + 2) / 2 <= k) bx++;
        while (bx * (bx + 1) / 2 > k) bx--;
        by = k - bx * (bx + 1) / 2;
    }
    const int mrow0 = by * 128;
    const int ncol0 = bx * 128;
    const bool diag = (MODE == 2) && (bx == by);

    const int r_ld = tid >> 2;
    const int q_ld = tid & 3;
    const float* Abase = A + (size_t)(mrow0 + r_ld) * DK + q_ld * 4;
    const float* Bbase = Bm + (size_t)(ncol0 + r_ld) * DK + q_ld * 4;
    const uint32_t dstOff = r_ld * (LDW * 4) + q_ld * 16;

#define ISSUE_CHUNK(c)                                                         \
    {                                                                          \
        const int s_ = (c) & (NSTAGE - 1);                                     \
        _Pragma("unroll")                                                      \
        for (int it = 0; it < 2; it++) {                                       \
            cp16(smA0 + s_ * STAGE_B + dstOff + it * 64 * (LDW * 4),           \
                 Abase + (size_t)it * 64 * DK + (c) * KC);                     \
            cp16(smB0 + s_ * STAGE_B + dstOff + it * 64 * (LDW * 4),           \
                 Bbase + (size_t)it * 64 * DK + (c) * KC);                     \
        }                                                                      \
        asm volatile("cp.async.commit_group;");                                \
    }

    float acc[4][4][4];
#pragma unroll
    for (int i = 0; i < 4; i++)
#pragma unroll
        for (int j = 0; j < 4; j++)
#pragma unroll
            for (int u = 0; u < 4; u++) acc[i][j][u] = 0.0f;

    ISSUE_CHUNK(0); ISSUE_CHUNK(1); ISSUE_CHUNK(2);

    const uint32_t aRow = warp_m * 64 + g;
    const uint32_t bRow = warp_n * 32 + g;

    for (int c = 0; c < NCH; c++) {
        if (c < NCH - 2)       asm volatile("cp.async.wait_group 2;");
        else if (c == NCH - 2) asm volatile("cp.async.wait_group 1;");
        else                   asm volatile("cp.async.wait_group 0;");
        __syncthreads();
        if (c + 3 < NCH) ISSUE_CHUNK(c + 3);

        const int s = c & (NSTAGE - 1);
        const uint32_t aBase = smA0 + s * STAGE_B;
        const uint32_t bBase = smB0 + s * STAGE_B;
#pragma unroll
        for (int ks = 0; ks < 2; ks++) {
            const int k0 = ks * 8 + t;
            uint32_t af[4][4], bf[4][2];
#pragma unroll
            for (int mt = 0; mt < 4; mt++) {
                uint32_t base = aBase + ((aRow + mt * 16) * LDW + k0) * 4;
                asm volatile("ld.shared.b32 %0, [%1];" : "=r"(af[mt][0]) : "r"(base));
                asm volatile("ld.shared.b32 %0, [%1];" : "=r"(af[mt][1]) : "r"(base + 8 * LDW * 4));
                asm volatile("ld.shared.b32 %0, [%1];" : "=r"(af[mt][2]) : "r"(base + 16));
                asm volatile("ld.shared.b32 %0, [%1];" : "=r"(af[mt][3]) : "r"(base + 8 * LDW * 4 + 16));
            }
#pragma unroll
            for (int nt = 0; nt < 4; nt++) {
                uint32_t base = bBase + ((bRow + nt * 8) * LDW + k0) * 4;
                asm volatile("ld.shared.b32 %0, [%1];" : "=r"(bf[nt][0]) : "r"(base));
                asm volatile("ld.shared.b32 %0, [%1];" : "=r"(bf[nt][1]) : "r"(base + 16));
            }
#pragma unroll
            for (int mt = 0; mt < 4; mt++)
#pragma unroll
                for (int nt = 0; nt < 4; nt++)
                    asm volatile(
                        "mma.sync.aligned.m16n8k8.row.col.f32.tf32.tf32.f32 "
                        "{%0,%1,%2,%3}, {%4,%5,%6,%7}, {%8,%9}, {%0,%1,%2,%3};"
                        : "+f"(acc[mt][nt][0]), "+f"(acc[mt][nt][1]),
                          "+f"(acc[mt][nt][2]), "+f"(acc[mt][nt][3])
                        : "r"(af[mt][0]), "r"(af[mt][1]), "r"(af[mt][2]), "r"(af[mt][3]),
                          "r"(bf[nt][0]), "r"(bf[nt][1]));
        }
    }
    asm volatile("cp.async.wait_group 0;");
    __syncthreads();   // pipeline smem now free for reuse

    // ---------------- epilogue ----------------
    const float* sqa = (MODE == 1) ? (const float*)g_sqx : (const float*)g_sqc;
    float sarow[8];
    int lbl[8];
#pragma unroll
    for (int mt = 0; mt < 4; mt++)
#pragma unroll
        for (int h = 0; h < 2; h++) {
            int r = mrow0 + warp_m * 64 + mt * 16 + h * 8 + g;
            sarow[mt * 2 + h] = sqa[r];
            if (MODE == 1)
                lbl[mt * 2 + h] = g_lab32 ? ((const int*)labels)[r]
                                          : (int)((const long long*)labels)[r];
        }
    float sbcol[8];
#pragma unroll
    for (int nt = 0; nt < 4; nt++) {
        int c0 = ncol0 + warp_n * 32 + nt * 8 + t * 2;
        sbcol[nt * 2] = g_sqc[c0];
        sbcol[nt * 2 + 1] = g_sqc[c0 + 1];
    }

    if (MODE == 1) {
        float minv[8];
#pragma unroll
        for (int i = 0; i < 8; i++) minv[i] = 3.0e38f;
#pragma unroll
        for (int mt = 0; mt < 4; mt++)
#pragma unroll
            for (int h = 0; h < 2; h++) {
                const int ri = mt * 2 + h;
                const int r = mrow0 + warp_m * 64 + mt * 16 + h * 8 + g;
                const float sa = sarow[ri];
#pragma unroll
                for (int nt = 0; nt < 4; nt++) {
                    const int c0 = ncol0 + warp_n * 32 + nt * 8 + t * 2;
                    float d0 = fminf(fmaxf(fmaf(-2.0f, acc[mt][nt][h * 2], sa + sbcol[nt * 2]), 1e-12f), 1e12f);
                    float d1 = fminf(fmaxf(fmaf(-2.0f, acc[mt][nt][h * 2 + 1], sa + sbcol[nt * 2 + 1]), 1e-12f), 1e12f);
                    if (c0 == lbl[ri]) g_dpos[r] = d0; else minv[ri] = fminf(minv[ri], d0);
                    if (c0 + 1 == lbl[ri]) g_dpos[r] = d1; else minv[ri] = fminf(minv[ri], d1);
                }
            }
#pragma unroll
        for (int ri = 0; ri < 8; ri++) {
            minv[ri] = fminf(minv[ri], __shfl_xor_sync(0xffffffffu, minv[ri], 1));
            minv[ri] = fminf(minv[ri], __shfl_xor_sync(0xffffffffu, minv[ri], 2));
        }
        if (t == 0) {
#pragma unroll
            for (int mt = 0; mt < 4; mt++)
#pragma unroll
                for (int h = 0; h < 2; h++) {
                    int r = mrow0 + warp_m * 64 + mt * 16 + h * 8 + g;
                    atomicMin(&g_rowmin_bits[r], __float_as_uint(minv[mt * 2 + h]));
                }
        }
    } else {
        float* smemT = (float*)smem;       // 128 x LDT floats = 67584 B
        ull rpack[8], cpack[8];
        float colpart[8], rowpart[8];
#pragma unroll
        for (int i = 0; i < 8; i++) {
            rpack[i] = 0xFFFFFFFFFFFFFFFFull;
            cpack[i] = 0xFFFFFFFFFFFFFFFFull;
            colpart[i] = 0.0f; rowpart[i] = 0.0f;
        }
#pragma unroll
        for (int mt = 0; mt < 4; mt++)
#pragma unroll
            for (int h = 0; h < 2; h++) {
                const int ri = mt * 2 + h;
                const int rl = warp_m * 64 + mt * 16 + h * 8 + g;
                const int r = mrow0 + rl;
                const float sa = sarow[ri];
#pragma unroll
                for (int nt = 0; nt < 4; nt++) {
                    const int cl = warp_n * 32 + nt * 8 + t * 2;
                    const int c0 = ncol0 + cl;
                    float d0 = fminf(fmaxf(fmaf(-2.0f, acc[mt][nt][h * 2], sa + sbcol[nt * 2]), 1e-12f), 1e12f);
                    float d1 = fminf(fmaxf(fmaf(-2.0f, acc[mt][nt][h * 2 + 1], sa + sbcol[nt * 2 + 1]), 1e-12f), 1e12f);
                    *(float2*)(out3 + (size_t)r * CN + c0) = make_float2(d0, d1);
                    smemT[cl * LDT + rl] = d0;
                    smemT[(cl + 1) * LDT + rl] = d1;
                    ull p0 = ((ull)__float_as_uint(d0) << 32) | (unsigned)c0;
                    ull p1 = ((ull)__float_as_uint(d1) << 32) | (unsigned)(c0 + 1);
                    if (c0 != r && p0 < rpack[ri]) rpack[ri] = p0;
                    if (c0 + 1 != r && p1 < rpack[ri]) rpack[ri] = p1;
                    ull q0 = ((ull)__float_as_uint(d0) << 32) | (unsigned)r;
                    ull q1 = ((ull)__float_as_uint(d1) << 32) | (unsigned)r;
                    if (c0 != r && q0 < cpack[nt * 2]) cpack[nt * 2] = q0;
                    if (c0 + 1 != r && q1 < cpack[nt * 2 + 1]) cpack[nt * 2 + 1] = q1;
                    colpart[nt * 2] += d0;
                    colpart[nt * 2 + 1] += d1;
                    rowpart[ri] += d0 + d1;
                }
            }
        // row side: reduce over t (4 lanes), atomics per row
#pragma unroll
        for (int ri = 0; ri < 8; ri++) {
            rpack[ri] = min(rpack[ri], __shfl_xor_sync(0xffffffffu, rpack[ri], 1));
            rpack[ri] = min(rpack[ri], __shfl_xor_sync(0xffffffffu, rpack[ri], 2));
            rowpart[ri] += __shfl_xor_sync(0xffffffffu, rowpart[ri], 1);
            rowpart[ri] += __shfl_xor_sync(0xffffffffu, rowpart[ri], 2);
        }
        if (t == 0) {
#pragma unroll
            for (int mt = 0; mt < 4; mt++)
#pragma unroll
                for (int h = 0; h < 2; h++) {
                    int r = mrow0 + warp_m * 64 + mt * 16 + h * 8 + g;
                    atomicMin(&g_rowpack[r], rpack[mt * 2 + h]);
                    if (!diag) atomicAdd(&g_colsum[r], rowpart[mt * 2 + h]);
                }
        }
        // col side: reduce over g (8 lanes), atomics per col
#pragma unroll
        for (int j = 0; j < 8; j++) {
            cpack[j] = min(cpack[j], __shfl_xor_sync(0xffffffffu, cpack[j], 4));
            cpack[j] = min(cpack[j], __shfl_xor_sync(0xffffffffu, cpack[j], 8));
            cpack[j] = min(cpack[j], __shfl_xor_sync(0xffffffffu, cpack[j], 16));
            colpart[j] += __shfl_xor_sync(0xffffffffu, colpart[j], 4);
            colpart[j] += __shfl_xor_sync(0xffffffffu, colpart[j], 8);
            colpart[j] += __shfl_xor_sync(0xffffffffu, colpart[j], 16);
        }
        if (g == 0) {
#pragma unroll
            for (int nt = 0; nt < 4; nt++) {
                int c0 = ncol0 + warp_n * 32 + nt * 8 + t * 2;
                atomicAdd(&g_colsum[c0], colpart[nt * 2]);
                atomicAdd(&g_colsum[c0 + 1], colpart[nt * 2 + 1]);
                if (!diag) {
                    atomicMin(&g_rowpack[c0], cpack[nt * 2]);
                    atomicMin(&g_rowpack[c0 + 1], cpack[nt * 2 + 1]);
                }
            }
        }
        // mirror store (off-diag only): float2 — out3 is only 8B aligned
        __syncthreads();
        if (!diag) {
            const int cl = tid >> 1;
            const int rh = tid & 1;
            const float* srcrow = &smemT[cl * LDT + rh * 64];
            float* dst = out3 + (size_t)(ncol0 + cl) * CN + mrow0 + rh * 64;
#pragma unroll
            for (int i = 0; i < 32; i++)
                *(float2*)(dst + i * 2) = *(const float2*)(srcrow + i * 2);
        }
    }
#undef ISSUE_CHUNK
}

// ---------------- finalize ----------------------------------------------------
__global__ void finalize_kernel(float* __restrict__ out) {
    __shared__ double red[256];
    int tid = threadIdx.x;

    double s = 0.0;
    for (int i = tid; i < BN; i += 256) {
        float dn = __uint_as_float(g_rowmin_bits[i]);
        s += (double)(g_dpos[i] / (dn + 1.0f));
    }
    red[tid] = s; __syncthreads();
    for (int o = 128; o > 0; o >>= 1) {
        if (tid < o) red[tid] += red[tid + o];
        __syncthreads();
    }
    if (tid == 0) out[0] = (float)(red[0] / (double)BN);
    __syncthreads();

    s = 0.0;
    for (int c = tid; c < CN; c += 256) {
        unsigned j = (unsigned)(g_rowpack[c] & 0xFFFFFFFFull);
        s += (double)g_colsum[j];
    }
    red[tid] = s; __syncthreads();
    for (int o = 128; o > 0; o >>= 1) {
        if (tid < o) red[tid] += red[tid + o];
        __syncthreads();
    }
    if (tid == 0) out[1] = (float)(-red[0] / ((double)CN * (double)CN));
}

// ---------------- launch -------------------------------------------------------
#define SMEM_BYTES (2 * NSTAGE * STAGE_B)    // 81920

extern "C" void kernel_launch(void* const* d_in, const int* in_sizes, int n_in,
                              void* d_out, int out_size) {
    const float* x = (const float*)d_in[0];
    const void* labels = d_in[1];
    const float* centers = (const float*)d_in[2];
    float* out = (float*)d_out;
    float* out3 = out + 2;

    cudaFuncSetAttribute(distmat_mma<1>, cudaFuncAttributeMaxDynamicSharedMemorySize, SMEM_BYTES);
    cudaFuncSetAttribute(distmat_mma<2>, cudaFuncAttributeMaxDynamicSharedMemorySize, SMEM_BYTES);

    init_kernel<<<(CN + 255) / 256, 256>>>();
    detect_kernel<<<(BN / 2 + 255) / 256, 256>>>((const unsigned*)labels);
    sqnorm_kernel<<<BN / 8, 256>>>(x, BN, 0);
    sqnorm_kernel<<<CN / 8, 256>>>(centers, CN, 1);

    dim3 grid1(CN / 128, BN / 128);
    distmat_mma<1><<<grid1, 256, SMEM_BYTES>>>(x, centers, labels, nullptr);
    int ntri = (CN / 128) * (CN / 128 + 1) / 2;   // 2080
    distmat_mma<2><<<ntri, 256, SMEM_BYTES>>>(centers, centers, nullptr, out3);

    finalize_kernel<<<1, 256>>>(out);
}